// round 3
// baseline (speedup 1.0000x reference)
#include <cuda_runtime.h>
#include <math.h>
#include <stdint.h>

#define NG   256
#define NG3  16777216
#define NW   (NG3/32)           // 524288 z-words per mask
#define SP   0.390625f          // 100/256, exact in f32

// combined grid: per z-word, lo32 = occ bits, hi32 = prot bits
static __device__ unsigned long long g_bits[NW];
static __device__ uint32_t           g_solvb[NW];

// ---- zero the splat grid (4 MB) ----
__global__ void zero_kernel() {
    unsigned i = blockIdx.x * blockDim.x + threadIdx.x;   // 262144 uint4
    if (i < NW / 2)
        reinterpret_cast<uint4*>(g_bits)[i] = make_uint4(0u, 0u, 0u, 0u);
}

// smallest float T with (s < T) <=> (sqrt_rn(s) < R)
__device__ __forceinline__ float cut_threshold(float R) {
    float t = __fmul_rn(R, R);
    while (__fsqrt_rn(t) >= R)
        t = __uint_as_float(__float_as_uint(t) - 1u);
    while (__fsqrt_rn(__uint_as_float(__float_as_uint(t) + 1u)) < R)
        t = __uint_as_float(__float_as_uint(t) + 1u);
    return __uint_as_float(__float_as_uint(t) + 1u);
}

// ---- splat: one warp per atom, branch-free 17-cell mask per (dx,dy) ----
__global__ void splat_kernel(const float* __restrict__ xyz,
                             const float* __restrict__ vdw,
                             int n_atoms) {
    int a = blockIdx.x * 4 + (threadIdx.x >> 5);
    if (a >= n_atoms) return;
    int lane = threadIdx.x & 31;
    float ax = xyz[3*a], ay = xyz[3*a+1], az = xyz[3*a+2];
    float vr = vdw[a];
    float R    = __fadd_rn(vr, 1.1f);
    float Tocc = cut_threshold(R);
    float Tpro = cut_threshold(vr);

    int bx = (int)floorf(__fdiv_rn(ax, SP));
    int by = (int)floorf(__fdiv_rn(ay, SP));
    int bz = (int)floorf(__fdiv_rn(az, SP));
    int zs = bz - 8;

    for (int p = lane; p < 289; p += 32) {
        int dx = p / 17 - 8;
        int dy = p % 17 - 8;
        int cx = bx + dx, cy = by + dy;
        float rx = __fsub_rn(__fmul_rn((float)cx, SP), ax);
        float ry = __fsub_rn(__fmul_rn((float)cy, SP), ay);
        float rxy2 = __fadd_rn(__fmul_rn(rx, rx), __fmul_rn(ry, ry));
        if (rxy2 >= Tocc) continue;           // exact: s >= rxy2

        unsigned mO = 0, mP = 0;
        #pragma unroll
        for (int j = 0; j < 17; ++j) {        // exact ref predicate per cell
            float rz = __fsub_rn(__fmul_rn((float)(zs + j), SP), az);
            float s  = __fadd_rn(rxy2, __fmul_rn(rz, rz));
            if (s < Tocc) mO |= 1u << j;
            if (s < Tpro) mP |= 1u << j;
        }
        if (!mO) continue;

        int s0 = zs & 255;
        int w0 = s0 >> 5, off = s0 & 31;
        unsigned long long osh = ((unsigned long long)mO) << off;
        unsigned long long psh = ((unsigned long long)mP) << off;
        int colbase = ((cx & 255) << 8) | (cy & 255);
        unsigned long long v0 = ((unsigned long long)(unsigned)psh << 32)
                              |  (unsigned long long)(unsigned)osh;
        unsigned long long v1 = ((unsigned long long)(unsigned)(psh >> 32) << 32)
                              |  (unsigned long long)(unsigned)(osh >> 32);
        if (v0) atomicOr(&g_bits[(w0 << 16) + colbase], v0);
        if (v1) atomicOr(&g_bits[((((w0 + 1) & 7)) << 16) + colbase], v1);
    }
}

// ---- classify: solv = ds | (nb & ~prot), bitwise erosion ----
__global__ void classify_kernel() {
    __shared__ uint32_t sD0[8 * 400];
    __shared__ uint32_t sD1[8 * 400];
    __shared__ uint32_t sD2[8 * 400];
    int bx0 = (blockIdx.x & 15) * 16;
    int by0 = (blockIdx.x >> 4) * 16;
    int t = threadIdx.x;

    for (int c = t; c < 400; c += 256) {
        int lx = c % 20, ly = c / 20;
        int gx = (bx0 + lx - 2) & 255;
        int gy = (by0 + ly - 2) & 255;
        int col = (gx << 8) | gy;
        uint32_t ds[8], d1[8], d2[8];
        #pragma unroll
        for (int i = 0; i < 8; i++)
            ds[i] = ~(uint32_t)g_bits[(i << 16) + col];
        #pragma unroll
        for (int i = 0; i < 8; i++)
            d1[i] = ds[i] | (ds[i] << 1) | (ds[(i+7)&7] >> 31)
                          | (ds[i] >> 1) | (ds[(i+1)&7] << 31);
        #pragma unroll
        for (int i = 0; i < 8; i++)
            d2[i] = d1[i] | (d1[i] << 1) | (d1[(i+7)&7] >> 31)
                          | (d1[i] >> 1) | (d1[(i+1)&7] << 31);
        #pragma unroll
        for (int i = 0; i < 8; i++) {
            sD0[i*400 + c] = ds[i];
            sD1[i*400 + c] = d1[i];
            sD2[i*400 + c] = d2[i];
        }
    }
    __syncthreads();

    int lx = (t & 15) + 2, ly = (t >> 4) + 2;
    int gx = (bx0 + lx - 2) & 255;
    int gy = (by0 + ly - 2) & 255;
    int col = (gx << 8) | gy;
    int cc = ly * 20 + lx;
    #pragma unroll
    for (int i = 0; i < 8; i++) {
        const uint32_t* D0 = sD0 + i * 400;
        const uint32_t* D1 = sD1 + i * 400;
        const uint32_t* D2 = sD2 + i * 400;
        uint32_t nb =
            D2[cc] | D2[cc+1]  | D2[cc-1]  | D2[cc+20] | D2[cc-20] |
            D1[cc+21] | D1[cc+19] | D1[cc-19] | D1[cc-21] |
            D1[cc+2]  | D1[cc-2]  | D1[cc+40] | D1[cc-40] |
            D0[cc+22] | D0[cc+18] | D0[cc-18] | D0[cc-22] |
            D0[cc+41] | D0[cc+39] | D0[cc-39] | D0[cc-41];
        uint32_t p = (uint32_t)(g_bits[(i << 16) + col] >> 32);
        g_solvb[(i << 16) + col] = D0[cc] | (nb & ~p);
    }
}

// ---- fused 27-tap blur from bits: one warp per z-column ----
__device__ __forceinline__ float4 f4add(float4 a, float4 b) {
    return make_float4(a.x+b.x, a.y+b.y, a.z+b.z, a.w+b.w);
}
__device__ __forceinline__ float4 f4fma(float s, float4 a, float4 b) {
    return make_float4(fmaf(s,a.x,b.x), fmaf(s,a.y,b.y),
                       fmaf(s,a.z,b.z), fmaf(s,a.w,b.w));
}

__global__ __launch_bounds__(256)
void blur_fused_kernel(float4* __restrict__ out, double a0d, double a1d) {
    __shared__ uint32_t sB[8][3][10];   // [word][x-1..x+1][y0-1..y0+8]
    __shared__ float4 sLc[64], sLe[64], sLk[64];

    int t = threadIdx.x;
    // build z-blur LUTs (weights in double, cast to f32)
    if (t < 192) {
        int grp = t >> 6, e = t & 63;
        double b[6];
        #pragma unroll
        for (int q = 0; q < 6; q++) b[q] = (double)((e >> q) & 1);
        double sc = (grp == 0) ? a0d * a0d : (grp == 1 ? a0d * a1d : a1d * a1d);
        float4 v = make_float4(
            (float)((a1d*b[0] + a0d*b[1] + a1d*b[2]) * sc),
            (float)((a1d*b[1] + a0d*b[2] + a1d*b[3]) * sc),
            (float)((a1d*b[2] + a0d*b[3] + a1d*b[4]) * sc),
            (float)((a1d*b[3] + a0d*b[4] + a1d*b[5]) * sc));
        if (grp == 0) sLc[e] = v; else if (grp == 1) sLe[e] = v; else sLk[e] = v;
    }

    int x  = blockIdx.x >> 5;
    int y0 = (blockIdx.x & 31) << 3;
    // stage 8 words x 3x10 columns
    if (t < 240) {
        int w = t / 30, r = t % 30;
        int ix = r / 10, iy = r % 10;
        int gx = (x + ix - 1) & 255;
        int gy = (y0 + iy - 1) & 255;
        sB[w][ix][iy] = g_solvb[(w << 16) | (gx << 8) | gy];
    }
    __syncthreads();

    int lane = t & 31;
    int wi   = t >> 5;                 // column y0+wi
    int col  = (x << 8) | (y0 + wi);

    // lanes 0..7: carry-save sum planes for their word
    uint32_t C=0, E0=0, E1=0, E2=0, K0=0, K1=0, K2=0, B31=0, B0p=0;
    if (lane < 8) {
        int w = lane;
        C = sB[w][1][wi+1];
        uint32_t ea = sB[w][0][wi+1], eb = sB[w][2][wi+1];
        uint32_t ec = sB[w][1][wi],   ed = sB[w][1][wi+2];
        uint32_t ka = sB[w][0][wi],   kb = sB[w][0][wi+2];
        uint32_t kc = sB[w][2][wi],   kd = sB[w][2][wi+2];
        {   uint32_t u = ea ^ eb, v = ea & eb, s2 = ec ^ ed, c2 = ec & ed;
            E0 = u ^ s2; uint32_t c3 = u & s2;
            E1 = v ^ c2 ^ c3;
            E2 = (v & c2) | (c3 & (v | c2)); }
        {   uint32_t u = ka ^ kb, v = ka & kb, s2 = kc ^ kd, c2 = kc & kd;
            K0 = u ^ s2; uint32_t c3 = u & s2;
            K1 = v ^ c2 ^ c3;
            K2 = (v & c2) | (c3 & (v | c2)); }
        B31 = ((C  >> 31) & 1)       | ((E0 >> 31) & 1) << 1
            | ((E1 >> 31) & 1) << 2  | ((E2 >> 31) & 1) << 3
            | ((K0 >> 31) & 1) << 4  | ((K1 >> 31) & 1) << 5
            | ((K2 >> 31) & 1) << 6;
        B0p = (C  & 1)      | (E0 & 1) << 1 | (E1 & 1) << 2 | (E2 & 1) << 3
            | (K0 & 1) << 4 | (K1 & 1) << 5 | (K2 & 1) << 6;
    }

    #pragma unroll
    for (int r = 0; r < 2; ++r) {
        int G   = lane + 32 * r;       // z-group 0..63
        int w   = G >> 3;
        int sub = G & 7;
        uint32_t c  = __shfl_sync(0xffffffffu, C,  w);
        uint32_t e0 = __shfl_sync(0xffffffffu, E0, w);
        uint32_t e1 = __shfl_sync(0xffffffffu, E1, w);
        uint32_t e2 = __shfl_sync(0xffffffffu, E2, w);
        uint32_t k0 = __shfl_sync(0xffffffffu, K0, w);
        uint32_t k1 = __shfl_sync(0xffffffffu, K1, w);
        uint32_t k2 = __shfl_sync(0xffffffffu, K2, w);
        uint32_t bp = __shfl_sync(0xffffffffu, B31, (w + 7) & 7);
        uint32_t bn = __shfl_sync(0xffffffffu, B0p, (w + 1) & 7);
        int sh = sub << 2;

        #define WIDX(P, p)  ((unsigned)(((((unsigned long long)((bn >> (p)) & 1)) << 33) \
                           | (((unsigned long long)(P)) << 1)                            \
                           | ((bp >> (p)) & 1)) >> sh) & 63u)

        float4 o = sLc[WIDX(c, 0)];
        o = f4add(o, sLe[WIDX(e0, 1)]);
        o = f4fma(2.0f, sLe[WIDX(e1, 2)], o);
        o = f4fma(4.0f, sLe[WIDX(e2, 3)], o);
        o = f4add(o, sLk[WIDX(k0, 4)]);
        o = f4fma(2.0f, sLk[WIDX(k1, 5)], o);
        o = f4fma(4.0f, sLk[WIDX(k2, 6)], o);
        out[(col << 6) + G] = o;
        #undef WIDX
    }
}

extern "C" void kernel_launch(void* const* d_in, const int* in_sizes, int n_in,
                              void* d_out, int out_size) {
    const float* xyz = (const float*)d_in[0];
    const float* vdw = (const float*)d_in[1];
    int n_atoms = in_sizes[1];

    double sigma = 1.1 / (100.0 / 256.0) / 4.0;
    double w = exp(-1.0 / (2.0 * sigma * sigma));
    double s = 1.0 + 2.0 * w;
    double a0d = 1.0 / s, a1d = w / s;

    zero_kernel     <<<1024, 256>>>();
    splat_kernel    <<<(n_atoms + 3) / 4, 128>>>(xyz, vdw, n_atoms);
    classify_kernel <<<256, 256>>>();
    blur_fused_kernel<<<8192, 256>>>((float4*)d_out, a0d, a1d);
}